// round 1
// baseline (speedup 1.0000x reference)
#include <cuda_runtime.h>
#include <cstdint>

#define HID   1024
#define ITR   704
#define NEXP  32
#define TTOK  8192
#define BM    64
#define BN    64
#define BK    16
#define ASTR  20     // A smem row stride (floats) — conflict-free for frag loads
#define BSTR  72     // B smem row stride (floats) — conflict-free for frag loads
#define MAXT  224
#define KT1   (HID/BK)   // 64
#define KT2   (ITR/BK)   // 44
#define NT1   (ITR/BN)   // 11  (gate & up handled together)
#define NT2   (HID/BN)   // 16
#define GRIDY 160        // >= max possible M-tiles (<=159)

// ---------------- device scratch (no cudaMalloc allowed) ----------------
__device__ int   d_tile_expert[MAXT];
__device__ int   d_tile_row0[MAXT];
__device__ int   d_tile_rows[MAXT];
__device__ int   d_ntiles;
__device__ float d_h[(size_t)TTOK * ITR];   // intermediate silu(gate)*up

// ---------------- helpers ----------------
__device__ __forceinline__ uint32_t f2tf32(float f) {
    uint32_t r;
    asm("cvt.rna.tf32.f32 %0, %1;" : "=r"(r) : "f"(f));
    return r;
}

__device__ __forceinline__ void mma_tf32(float c[4], const uint32_t a[4], const uint32_t b[2]) {
    asm volatile(
        "mma.sync.aligned.m16n8k8.row.col.f32.tf32.tf32.f32 "
        "{%0,%1,%2,%3}, {%4,%5,%6,%7}, {%8,%9}, {%0,%1,%2,%3};\n"
        : "+f"(c[0]), "+f"(c[1]), "+f"(c[2]), "+f"(c[3])
        : "r"(a[0]), "r"(a[1]), "r"(a[2]), "r"(a[3]), "r"(b[0]), "r"(b[1]));
}

// ---------------- setup: build ragged tile list ----------------
__global__ void setup_kernel(const int* __restrict__ tpe) {
    if (threadIdx.x == 0) {
        int off = 0, nt = 0;
        for (int e = 0; e < NEXP; e++) {
            int c = tpe[e];
            for (int r = 0; r < c; r += BM) {
                d_tile_expert[nt] = e;
                d_tile_row0[nt]   = off + r;
                d_tile_rows[nt]   = min(BM, c - r);
                nt++;
            }
            off += c;
        }
        d_ntiles = nt;
    }
}

// ---------------- GEMM1: x @ w1w3 -> silu(gate)*up -> d_h ----------------
// grid = (NT1, GRIDY), block = 256. Each block: 64 rows x 64 cols of gate AND up.
__global__ __launch_bounds__(256, 2)
void gemm1_kernel(const float* __restrict__ x, const float* __restrict__ w1w3) {
    __shared__ __align__(16) uint32_t As [2][BM * ASTR];
    __shared__ __align__(16) uint32_t Bgs[2][BK * BSTR];
    __shared__ __align__(16) uint32_t Bus[2][BK * BSTR];

    int tile = blockIdx.y;
    if (tile >= d_ntiles) return;
    const int e    = d_tile_expert[tile];
    const int row0 = d_tile_row0[tile];
    const int rows = d_tile_rows[tile];
    const int n0   = blockIdx.x * BN;

    const int tid  = threadIdx.x;
    const int lane = tid & 31;
    const int warp = tid >> 5;
    const int wm   = (warp & 1) * 32;    // warp M offset within tile
    const int wn   = (warp >> 1) * 16;   // warp N offset within tile

    // global load mapping
    const int arow = tid >> 2, acol = (tid & 3) << 2;     // A: 64x16, float4 each
    const int brow = tid >> 4, bcol = (tid & 15) << 2;    // B: 16x64, float4 each
    const bool aok = (arow < rows);
    const float* ap  = x + (size_t)(row0 + arow) * HID + acol;
    const float* bgp = w1w3 + (size_t)e * HID * (2 * ITR) + (size_t)brow * (2 * ITR) + n0 + bcol;
    const float* bup = bgp + ITR;

    float4 ra = make_float4(0.f, 0.f, 0.f, 0.f), rg, ru;
    if (aok) ra = *(const float4*)ap;
    rg = *(const float4*)bgp;
    ru = *(const float4*)bup;

    float accg[2][2][4] = {}, accu[2][2][4] = {};

    int pb = 0;
    // prime stage 0
    {
        uint4 q;
        q.x = f2tf32(ra.x); q.y = f2tf32(ra.y); q.z = f2tf32(ra.z); q.w = f2tf32(ra.w);
        *(uint4*)&As[0][arow * ASTR + acol] = q;
        q.x = f2tf32(rg.x); q.y = f2tf32(rg.y); q.z = f2tf32(rg.z); q.w = f2tf32(rg.w);
        *(uint4*)&Bgs[0][brow * BSTR + bcol] = q;
        q.x = f2tf32(ru.x); q.y = f2tf32(ru.y); q.z = f2tf32(ru.z); q.w = f2tf32(ru.w);
        *(uint4*)&Bus[0][brow * BSTR + bcol] = q;
    }
    __syncthreads();

    #pragma unroll 1
    for (int kt = 0; kt < KT1; kt++) {
        const int nk = kt + 1;
        if (nk < KT1) {
            if (aok) ra = *(const float4*)(ap + (size_t)nk * BK);
            rg = *(const float4*)(bgp + (size_t)nk * BK * (2 * ITR));
            ru = *(const float4*)(bup + (size_t)nk * BK * (2 * ITR));
        }

        // ---- compute on buffer pb ----
        #pragma unroll
        for (int ks = 0; ks < BK; ks += 8) {
            uint32_t af[2][4];
            #pragma unroll
            for (int mi = 0; mi < 2; mi++) {
                const int r = wm + mi * 16 + (lane >> 2);
                const int c = ks + (lane & 3);
                af[mi][0] = As[pb][r * ASTR + c];
                af[mi][1] = As[pb][(r + 8) * ASTR + c];
                af[mi][2] = As[pb][r * ASTR + c + 4];
                af[mi][3] = As[pb][(r + 8) * ASTR + c + 4];
            }
            uint32_t bgf[2][2], buf_[2][2];
            #pragma unroll
            for (int ni = 0; ni < 2; ni++) {
                const int n = wn + ni * 8 + (lane >> 2);
                const int k = ks + (lane & 3);
                bgf[ni][0] = Bgs[pb][k * BSTR + n];
                bgf[ni][1] = Bgs[pb][(k + 4) * BSTR + n];
                buf_[ni][0] = Bus[pb][k * BSTR + n];
                buf_[ni][1] = Bus[pb][(k + 4) * BSTR + n];
            }
            #pragma unroll
            for (int mi = 0; mi < 2; mi++)
                #pragma unroll
                for (int ni = 0; ni < 2; ni++) {
                    mma_tf32(accg[mi][ni], af[mi], bgf[ni]);
                    mma_tf32(accu[mi][ni], af[mi], buf_[ni]);
                }
        }

        if (nk < KT1) {
            pb ^= 1;
            uint4 q;
            q.x = f2tf32(ra.x); q.y = f2tf32(ra.y); q.z = f2tf32(ra.z); q.w = f2tf32(ra.w);
            *(uint4*)&As[pb][arow * ASTR + acol] = q;
            q.x = f2tf32(rg.x); q.y = f2tf32(rg.y); q.z = f2tf32(rg.z); q.w = f2tf32(rg.w);
            *(uint4*)&Bgs[pb][brow * BSTR + bcol] = q;
            q.x = f2tf32(ru.x); q.y = f2tf32(ru.y); q.z = f2tf32(ru.z); q.w = f2tf32(ru.w);
            *(uint4*)&Bus[pb][brow * BSTR + bcol] = q;
        }
        __syncthreads();
    }

    // ---- epilogue: h = silu(gate) * up ----
    #pragma unroll
    for (int mi = 0; mi < 2; mi++) {
        const int rb = wm + mi * 16 + (lane >> 2);
        #pragma unroll
        for (int ni = 0; ni < 2; ni++) {
            const int cb = n0 + wn + ni * 8 + 2 * (lane & 3);
            if (rb < rows) {
                float g0 = accg[mi][ni][0], g1 = accg[mi][ni][1];
                float2 v;
                v.x = accu[mi][ni][0] * g0 / (1.f + __expf(-g0));
                v.y = accu[mi][ni][1] * g1 / (1.f + __expf(-g1));
                *(float2*)&d_h[(size_t)(row0 + rb) * ITR + cb] = v;
            }
            if (rb + 8 < rows) {
                float g2 = accg[mi][ni][2], g3 = accg[mi][ni][3];
                float2 v;
                v.x = accu[mi][ni][2] * g2 / (1.f + __expf(-g2));
                v.y = accu[mi][ni][3] * g3 / (1.f + __expf(-g3));
                *(float2*)&d_h[(size_t)(row0 + rb + 8) * ITR + cb] = v;
            }
        }
    }
}

// ---------------- GEMM2: d_h @ w2 -> out ----------------
__global__ __launch_bounds__(256, 2)
void gemm2_kernel(const float* __restrict__ w2, float* __restrict__ out) {
    __shared__ __align__(16) uint32_t As[2][BM * ASTR];
    __shared__ __align__(16) uint32_t Bs[2][BK * BSTR];

    int tile = blockIdx.y;
    if (tile >= d_ntiles) return;
    const int e    = d_tile_expert[tile];
    const int row0 = d_tile_row0[tile];
    const int rows = d_tile_rows[tile];
    const int n0   = blockIdx.x * BN;

    const int tid  = threadIdx.x;
    const int lane = tid & 31;
    const int warp = tid >> 5;
    const int wm   = (warp & 1) * 32;
    const int wn   = (warp >> 1) * 16;

    const int arow = tid >> 2, acol = (tid & 3) << 2;
    const int brow = tid >> 4, bcol = (tid & 15) << 2;
    const bool aok = (arow < rows);
    const float* ap = d_h + (size_t)(row0 + arow) * ITR + acol;
    const float* bp = w2 + (size_t)e * ITR * HID + (size_t)brow * HID + n0 + bcol;

    float4 ra = make_float4(0.f, 0.f, 0.f, 0.f), rb4;
    if (aok) ra = *(const float4*)ap;
    rb4 = *(const float4*)bp;

    float acc[2][2][4] = {};

    int pb = 0;
    {
        uint4 q;
        q.x = f2tf32(ra.x); q.y = f2tf32(ra.y); q.z = f2tf32(ra.z); q.w = f2tf32(ra.w);
        *(uint4*)&As[0][arow * ASTR + acol] = q;
        q.x = f2tf32(rb4.x); q.y = f2tf32(rb4.y); q.z = f2tf32(rb4.z); q.w = f2tf32(rb4.w);
        *(uint4*)&Bs[0][brow * BSTR + bcol] = q;
    }
    __syncthreads();

    #pragma unroll 1
    for (int kt = 0; kt < KT2; kt++) {
        const int nk = kt + 1;
        if (nk < KT2) {
            if (aok) ra = *(const float4*)(ap + (size_t)nk * BK);
            rb4 = *(const float4*)(bp + (size_t)nk * BK * HID);
        }

        #pragma unroll
        for (int ks = 0; ks < BK; ks += 8) {
            uint32_t af[2][4];
            #pragma unroll
            for (int mi = 0; mi < 2; mi++) {
                const int r = wm + mi * 16 + (lane >> 2);
                const int c = ks + (lane & 3);
                af[mi][0] = As[pb][r * ASTR + c];
                af[mi][1] = As[pb][(r + 8) * ASTR + c];
                af[mi][2] = As[pb][r * ASTR + c + 4];
                af[mi][3] = As[pb][(r + 8) * ASTR + c + 4];
            }
            uint32_t bf[2][2];
            #pragma unroll
            for (int ni = 0; ni < 2; ni++) {
                const int n = wn + ni * 8 + (lane >> 2);
                const int k = ks + (lane & 3);
                bf[ni][0] = Bs[pb][k * BSTR + n];
                bf[ni][1] = Bs[pb][(k + 4) * BSTR + n];
            }
            #pragma unroll
            for (int mi = 0; mi < 2; mi++)
                #pragma unroll
                for (int ni = 0; ni < 2; ni++)
                    mma_tf32(acc[mi][ni], af[mi], bf[ni]);
        }

        if (nk < KT2) {
            pb ^= 1;
            uint4 q;
            q.x = f2tf32(ra.x); q.y = f2tf32(ra.y); q.z = f2tf32(ra.z); q.w = f2tf32(ra.w);
            *(uint4*)&As[pb][arow * ASTR + acol] = q;
            q.x = f2tf32(rb4.x); q.y = f2tf32(rb4.y); q.z = f2tf32(rb4.z); q.w = f2tf32(rb4.w);
            *(uint4*)&Bs[pb][brow * BSTR + bcol] = q;
        }
        __syncthreads();
    }

    #pragma unroll
    for (int mi = 0; mi < 2; mi++) {
        const int rb = wm + mi * 16 + (lane >> 2);
        #pragma unroll
        for (int ni = 0; ni < 2; ni++) {
            const int cb = n0 + wn + ni * 8 + 2 * (lane & 3);
            if (rb < rows) {
                float2 v = make_float2(acc[mi][ni][0], acc[mi][ni][1]);
                *(float2*)&out[(size_t)(row0 + rb) * HID + cb] = v;
            }
            if (rb + 8 < rows) {
                float2 v = make_float2(acc[mi][ni][2], acc[mi][ni][3]);
                *(float2*)&out[(size_t)(row0 + rb + 8) * HID + cb] = v;
            }
        }
    }
}

// ---------------- launch ----------------
extern "C" void kernel_launch(void* const* d_in, const int* in_sizes, int n_in,
                              void* d_out, int out_size) {
    const float* x    = (const float*)d_in[0];
    const int*   tpe  = (const int*)d_in[1];
    const float* w1w3 = (const float*)d_in[2];
    const float* w2   = (const float*)d_in[3];
    float*       out  = (float*)d_out;

    setup_kernel<<<1, 32>>>(tpe);
    gemm1_kernel<<<dim3(NT1, GRIDY), 256>>>(x, w1w3);
    gemm2_kernel<<<dim3(NT2, GRIDY), 256>>>(w2, out);
}

// round 2
// speedup vs baseline: 1.0010x; 1.0010x over previous
#include <cuda_runtime.h>
#include <cstdint>

#define HID   1024
#define ITR   704
#define NEXP  32
#define TTOK  8192
#define BM    64
#define BN    64
#define BK    16
#define ASTR  20     // A smem row stride (floats) — conflict-free for frag loads
#define BSTR  72     // B smem row stride (floats) — conflict-free for frag loads
#define MAXT  224
#define KT1   (HID/BK)   // 64
#define KT2   (ITR/BK)   // 44
#define NT1   (ITR/BN)   // 11  (gate & up handled together)
#define NT2   (HID/BN)   // 16
#define GRIDY 160        // >= max possible M-tiles (<=159)

// ---------------- device scratch (no cudaMalloc allowed) ----------------
__device__ int   d_tile_expert[MAXT];
__device__ int   d_tile_row0[MAXT];
__device__ int   d_tile_rows[MAXT];
__device__ int   d_ntiles;
__device__ float d_h[(size_t)TTOK * ITR];   // intermediate silu(gate)*up

// ---------------- helpers ----------------
__device__ __forceinline__ uint32_t f2tf32(float f) {
    uint32_t r;
    asm("cvt.rna.tf32.f32 %0, %1;" : "=r"(r) : "f"(f));
    return r;
}

__device__ __forceinline__ void mma_tf32(float c[4], const uint32_t a[4], const uint32_t b[2]) {
    asm volatile(
        "mma.sync.aligned.m16n8k8.row.col.f32.tf32.tf32.f32 "
        "{%0,%1,%2,%3}, {%4,%5,%6,%7}, {%8,%9}, {%0,%1,%2,%3};\n"
        : "+f"(c[0]), "+f"(c[1]), "+f"(c[2]), "+f"(c[3])
        : "r"(a[0]), "r"(a[1]), "r"(a[2]), "r"(a[3]), "r"(b[0]), "r"(b[1]));
}

// ---------------- setup: build ragged tile list ----------------
__global__ void setup_kernel(const int* __restrict__ tpe) {
    if (threadIdx.x == 0) {
        int off = 0, nt = 0;
        for (int e = 0; e < NEXP; e++) {
            int c = tpe[e];
            for (int r = 0; r < c; r += BM) {
                d_tile_expert[nt] = e;
                d_tile_row0[nt]   = off + r;
                d_tile_rows[nt]   = min(BM, c - r);
                nt++;
            }
            off += c;
        }
        d_ntiles = nt;
    }
}

// ---------------- GEMM1: x @ w1w3 -> silu(gate)*up -> d_h ----------------
// grid = (NT1, GRIDY), block = 256. Each block: 64 rows x 64 cols of gate AND up.
__global__ __launch_bounds__(256, 2)
void gemm1_kernel(const float* __restrict__ x, const float* __restrict__ w1w3) {
    __shared__ __align__(16) uint32_t As [2][BM * ASTR];
    __shared__ __align__(16) uint32_t Bgs[2][BK * BSTR];
    __shared__ __align__(16) uint32_t Bus[2][BK * BSTR];

    int tile = blockIdx.y;
    if (tile >= d_ntiles) return;
    const int e    = d_tile_expert[tile];
    const int row0 = d_tile_row0[tile];
    const int rows = d_tile_rows[tile];
    const int n0   = blockIdx.x * BN;

    const int tid  = threadIdx.x;
    const int lane = tid & 31;
    const int warp = tid >> 5;
    const int wm   = (warp & 1) * 32;    // warp M offset within tile
    const int wn   = (warp >> 1) * 16;   // warp N offset within tile

    // global load mapping
    const int arow = tid >> 2, acol = (tid & 3) << 2;     // A: 64x16, float4 each
    const int brow = tid >> 4, bcol = (tid & 15) << 2;    // B: 16x64, float4 each
    const bool aok = (arow < rows);
    const float* ap  = x + (size_t)(row0 + arow) * HID + acol;
    const float* bgp = w1w3 + (size_t)e * HID * (2 * ITR) + (size_t)brow * (2 * ITR) + n0 + bcol;
    const float* bup = bgp + ITR;

    float4 ra = make_float4(0.f, 0.f, 0.f, 0.f), rg, ru;
    if (aok) ra = *(const float4*)ap;
    rg = *(const float4*)bgp;
    ru = *(const float4*)bup;

    float accg[2][2][4] = {}, accu[2][2][4] = {};

    int pb = 0;
    // prime stage 0
    {
        uint4 q;
        q.x = f2tf32(ra.x); q.y = f2tf32(ra.y); q.z = f2tf32(ra.z); q.w = f2tf32(ra.w);
        *(uint4*)&As[0][arow * ASTR + acol] = q;
        q.x = f2tf32(rg.x); q.y = f2tf32(rg.y); q.z = f2tf32(rg.z); q.w = f2tf32(rg.w);
        *(uint4*)&Bgs[0][brow * BSTR + bcol] = q;
        q.x = f2tf32(ru.x); q.y = f2tf32(ru.y); q.z = f2tf32(ru.z); q.w = f2tf32(ru.w);
        *(uint4*)&Bus[0][brow * BSTR + bcol] = q;
    }
    __syncthreads();

    #pragma unroll 1
    for (int kt = 0; kt < KT1; kt++) {
        const int nk = kt + 1;
        if (nk < KT1) {
            if (aok) ra = *(const float4*)(ap + (size_t)nk * BK);
            rg = *(const float4*)(bgp + (size_t)nk * BK * (2 * ITR));
            ru = *(const float4*)(bup + (size_t)nk * BK * (2 * ITR));
        }

        // ---- compute on buffer pb ----
        #pragma unroll
        for (int ks = 0; ks < BK; ks += 8) {
            uint32_t af[2][4];
            #pragma unroll
            for (int mi = 0; mi < 2; mi++) {
                const int r = wm + mi * 16 + (lane >> 2);
                const int c = ks + (lane & 3);
                af[mi][0] = As[pb][r * ASTR + c];
                af[mi][1] = As[pb][(r + 8) * ASTR + c];
                af[mi][2] = As[pb][r * ASTR + c + 4];
                af[mi][3] = As[pb][(r + 8) * ASTR + c + 4];
            }
            uint32_t bgf[2][2], buf_[2][2];
            #pragma unroll
            for (int ni = 0; ni < 2; ni++) {
                const int n = wn + ni * 8 + (lane >> 2);
                const int k = ks + (lane & 3);
                bgf[ni][0] = Bgs[pb][k * BSTR + n];
                bgf[ni][1] = Bgs[pb][(k + 4) * BSTR + n];
                buf_[ni][0] = Bus[pb][k * BSTR + n];
                buf_[ni][1] = Bus[pb][(k + 4) * BSTR + n];
            }
            #pragma unroll
            for (int mi = 0; mi < 2; mi++)
                #pragma unroll
                for (int ni = 0; ni < 2; ni++) {
                    mma_tf32(accg[mi][ni], af[mi], bgf[ni]);
                    mma_tf32(accu[mi][ni], af[mi], buf_[ni]);
                }
        }

        if (nk < KT1) {
            pb ^= 1;
            uint4 q;
            q.x = f2tf32(ra.x); q.y = f2tf32(ra.y); q.z = f2tf32(ra.z); q.w = f2tf32(ra.w);
            *(uint4*)&As[pb][arow * ASTR + acol] = q;
            q.x = f2tf32(rg.x); q.y = f2tf32(rg.y); q.z = f2tf32(rg.z); q.w = f2tf32(rg.w);
            *(uint4*)&Bgs[pb][brow * BSTR + bcol] = q;
            q.x = f2tf32(ru.x); q.y = f2tf32(ru.y); q.z = f2tf32(ru.z); q.w = f2tf32(ru.w);
            *(uint4*)&Bus[pb][brow * BSTR + bcol] = q;
        }
        __syncthreads();
    }

    // ---- epilogue: h = silu(gate) * up ----
    #pragma unroll
    for (int mi = 0; mi < 2; mi++) {
        const int rb = wm + mi * 16 + (lane >> 2);
        #pragma unroll
        for (int ni = 0; ni < 2; ni++) {
            const int cb = n0 + wn + ni * 8 + 2 * (lane & 3);
            if (rb < rows) {
                float g0 = accg[mi][ni][0], g1 = accg[mi][ni][1];
                float2 v;
                v.x = accu[mi][ni][0] * g0 / (1.f + __expf(-g0));
                v.y = accu[mi][ni][1] * g1 / (1.f + __expf(-g1));
                *(float2*)&d_h[(size_t)(row0 + rb) * ITR + cb] = v;
            }
            if (rb + 8 < rows) {
                float g2 = accg[mi][ni][2], g3 = accg[mi][ni][3];
                float2 v;
                v.x = accu[mi][ni][2] * g2 / (1.f + __expf(-g2));
                v.y = accu[mi][ni][3] * g3 / (1.f + __expf(-g3));
                *(float2*)&d_h[(size_t)(row0 + rb + 8) * ITR + cb] = v;
            }
        }
    }
}

// ---------------- GEMM2: d_h @ w2 -> out ----------------
__global__ __launch_bounds__(256, 2)
void gemm2_kernel(const float* __restrict__ w2, float* __restrict__ out) {
    __shared__ __align__(16) uint32_t As[2][BM * ASTR];
    __shared__ __align__(16) uint32_t Bs[2][BK * BSTR];

    int tile = blockIdx.y;
    if (tile >= d_ntiles) return;
    const int e    = d_tile_expert[tile];
    const int row0 = d_tile_row0[tile];
    const int rows = d_tile_rows[tile];
    const int n0   = blockIdx.x * BN;

    const int tid  = threadIdx.x;
    const int lane = tid & 31;
    const int warp = tid >> 5;
    const int wm   = (warp & 1) * 32;
    const int wn   = (warp >> 1) * 16;

    const int arow = tid >> 2, acol = (tid & 3) << 2;
    const int brow = tid >> 4, bcol = (tid & 15) << 2;
    const bool aok = (arow < rows);
    const float* ap = d_h + (size_t)(row0 + arow) * ITR + acol;
    const float* bp = w2 + (size_t)e * ITR * HID + (size_t)brow * HID + n0 + bcol;

    float4 ra = make_float4(0.f, 0.f, 0.f, 0.f), rb4;
    if (aok) ra = *(const float4*)ap;
    rb4 = *(const float4*)bp;

    float acc[2][2][4] = {};

    int pb = 0;
    {
        uint4 q;
        q.x = f2tf32(ra.x); q.y = f2tf32(ra.y); q.z = f2tf32(ra.z); q.w = f2tf32(ra.w);
        *(uint4*)&As[0][arow * ASTR + acol] = q;
        q.x = f2tf32(rb4.x); q.y = f2tf32(rb4.y); q.z = f2tf32(rb4.z); q.w = f2tf32(rb4.w);
        *(uint4*)&Bs[0][brow * BSTR + bcol] = q;
    }
    __syncthreads();

    #pragma unroll 1
    for (int kt = 0; kt < KT2; kt++) {
        const int nk = kt + 1;
        if (nk < KT2) {
            if (aok) ra = *(const float4*)(ap + (size_t)nk * BK);
            rb4 = *(const float4*)(bp + (size_t)nk * BK * HID);
        }

        #pragma unroll
        for (int ks = 0; ks < BK; ks += 8) {
            uint32_t af[2][4];
            #pragma unroll
            for (int mi = 0; mi < 2; mi++) {
                const int r = wm + mi * 16 + (lane >> 2);
                const int c = ks + (lane & 3);
                af[mi][0] = As[pb][r * ASTR + c];
                af[mi][1] = As[pb][(r + 8) * ASTR + c];
                af[mi][2] = As[pb][r * ASTR + c + 4];
                af[mi][3] = As[pb][(r + 8) * ASTR + c + 4];
            }
            uint32_t bf[2][2];
            #pragma unroll
            for (int ni = 0; ni < 2; ni++) {
                const int n = wn + ni * 8 + (lane >> 2);
                const int k = ks + (lane & 3);
                bf[ni][0] = Bs[pb][k * BSTR + n];
                bf[ni][1] = Bs[pb][(k + 4) * BSTR + n];
            }
            #pragma unroll
            for (int mi = 0; mi < 2; mi++)
                #pragma unroll
                for (int ni = 0; ni < 2; ni++)
                    mma_tf32(acc[mi][ni], af[mi], bf[ni]);
        }

        if (nk < KT2) {
            pb ^= 1;
            uint4 q;
            q.x = f2tf32(ra.x); q.y = f2tf32(ra.y); q.z = f2tf32(ra.z); q.w = f2tf32(ra.w);
            *(uint4*)&As[pb][arow * ASTR + acol] = q;
            q.x = f2tf32(rb4.x); q.y = f2tf32(rb4.y); q.z = f2tf32(rb4.z); q.w = f2tf32(rb4.w);
            *(uint4*)&Bs[pb][brow * BSTR + bcol] = q;
        }
        __syncthreads();
    }

    #pragma unroll
    for (int mi = 0; mi < 2; mi++) {
        const int rb = wm + mi * 16 + (lane >> 2);
        #pragma unroll
        for (int ni = 0; ni < 2; ni++) {
            const int cb = n0 + wn + ni * 8 + 2 * (lane & 3);
            if (rb < rows) {
                float2 v = make_float2(acc[mi][ni][0], acc[mi][ni][1]);
                *(float2*)&out[(size_t)(row0 + rb) * HID + cb] = v;
            }
            if (rb + 8 < rows) {
                float2 v = make_float2(acc[mi][ni][2], acc[mi][ni][3]);
                *(float2*)&out[(size_t)(row0 + rb + 8) * HID + cb] = v;
            }
        }
    }
}

// ---------------- launch ----------------
extern "C" void kernel_launch(void* const* d_in, const int* in_sizes, int n_in,
                              void* d_out, int out_size) {
    const float* x    = (const float*)d_in[0];
    const int*   tpe  = (const int*)d_in[1];
    const float* w1w3 = (const float*)d_in[2];
    const float* w2   = (const float*)d_in[3];
    float*       out  = (float*)d_out;

    setup_kernel<<<1, 32>>>(tpe);
    gemm1_kernel<<<dim3(NT1, GRIDY), 256>>>(x, w1w3);
    gemm2_kernel<<<dim3(NT2, GRIDY), 256>>>(w2, out);
}

// round 4
// speedup vs baseline: 1.3398x; 1.3385x over previous
#include <cuda_runtime.h>
#include <cstdint>

#define HID 1024
#define ITR 704
#define NEXP 32
#define TTOK 8192
#define MAXT 96
#define ASTR 36
#define BSTR 136
#define AWORDS (128*ASTR)       // 4608 words
#define BWORDS (32*BSTR)        // 4352 words
#define STW (AWORDS+BWORDS)     // 8960 words/stage
#define SMEMSZ (2*STW*4)        // 71680 bytes

__device__ int   d_te[MAXT], d_tr0[MAXT], d_trs[MAXT], d_nt;
__device__ float d_hbuf[(size_t)TTOK * ITR];

__device__ __forceinline__ uint32_t f2t(float f) {
    uint32_t r; asm("cvt.rna.tf32.f32 %0, %1;" : "=r"(r) : "f"(f)); return r;
}
__device__ __forceinline__ void mma8(float* c, const uint32_t* a, const uint32_t* b) {
    asm volatile(
        "mma.sync.aligned.m16n8k8.row.col.f32.tf32.tf32.f32 "
        "{%0,%1,%2,%3},{%4,%5,%6,%7},{%8,%9},{%0,%1,%2,%3};"
        : "+f"(c[0]), "+f"(c[1]), "+f"(c[2]), "+f"(c[3])
        : "r"(a[0]), "r"(a[1]), "r"(a[2]), "r"(a[3]), "r"(b[0]), "r"(b[1]));
}

__global__ void setup_kernel(const int* __restrict__ tpe) {
    if (threadIdx.x == 0) {
        int off = 0, nt = 0;
        for (int e = 0; e < NEXP; e++) {
            int c = tpe[e];
            for (int r = 0; r < c; r += 128) {
                d_te[nt] = e; d_tr0[nt] = off + r; d_trs[nt] = min(128, c - r); nt++;
            }
            off += c;
        }
        d_nt = nt;
    }
}

template <int G>
__global__ __launch_bounds__(256, 1) void moe_gemm(const float* __restrict__ Ain,
                                                   const float* __restrict__ Bin,
                                                   float* __restrict__ Out) {
    extern __shared__ __align__(16) uint32_t sm[];
    const int tile = blockIdx.y;
    if (tile >= d_nt) return;
    constexpr int KT   = (G == 1) ? 32 : 22;
    constexpr int AST  = (G == 1) ? HID : ITR;
    constexpr int BROW = (G == 1) ? (2 * ITR) : HID;
    const int e = d_te[tile], row0 = d_tr0[tile], rows = d_trs[tile];
    const int n0 = blockIdx.x * ((G == 1) ? 64 : 128);

    const int tid = threadIdx.x, w = tid >> 5, l = tid & 31;
    const int wm = (w & 1) * 64;
    const int wn = (w >> 1) * ((G == 1) ? 16 : 32);

    const float* Ag = (G == 1) ? Ain : d_hbuf;
    const float* Bg = Bin + (size_t)e * ((G == 1) ? (size_t)HID * (2 * ITR)
                                                  : (size_t)ITR * HID);

    // A loads: 2 rows (ar, ar+64), 8 consecutive k each (2 float4)
    const int ar = tid >> 2, ak = (tid & 3) * 8;
    const size_t aoff0 = (size_t)min(row0 + ar, TTOK - 1) * AST + ak;
    const size_t aoff1 = (size_t)min(row0 + ar + 64, TTOK - 1) * AST + ak;
    const int asw0 = ar * ASTR + ak, asw1 = (ar + 64) * ASTR + ak;

    // B loads: row k = tid>>3, 4 cols x 4 chunks (n += 32j)
    const int bk = tid >> 3, bn = (tid & 7) * 4;
    size_t boff[4]; int bsw[4];
    #pragma unroll
    for (int j = 0; j < 4; j++) {
        int n = bn + 32 * j;
        int col = (G == 1) ? ((n < 64) ? (n0 + n) : (ITR + n0 + n - 64)) : (n0 + n);
        boff[j] = (size_t)bk * BROW + col;
        bsw[j]  = bk * BSTR + n;
    }

    float4 av[4], bv[4];
    #define LDGA(it) do { const size_t ko = (size_t)(it) * 32; \
        av[0] = *(const float4*)(Ag + aoff0 + ko); \
        av[1] = *(const float4*)(Ag + aoff0 + ko + 4); \
        av[2] = *(const float4*)(Ag + aoff1 + ko); \
        av[3] = *(const float4*)(Ag + aoff1 + ko + 4); \
        _Pragma("unroll") for (int j = 0; j < 4; j++) \
            bv[j] = *(const float4*)(Bg + boff[j] + (size_t)(it) * 32 * BROW); \
    } while (0)

    #define STSA(st) do { uint32_t* Asm = sm + (st) * STW; uint32_t* Bsm = Asm + AWORDS; \
        *(uint4*)(Asm + asw0)     = make_uint4(f2t(av[0].x), f2t(av[0].y), f2t(av[0].z), f2t(av[0].w)); \
        *(uint4*)(Asm + asw0 + 4) = make_uint4(f2t(av[1].x), f2t(av[1].y), f2t(av[1].z), f2t(av[1].w)); \
        *(uint4*)(Asm + asw1)     = make_uint4(f2t(av[2].x), f2t(av[2].y), f2t(av[2].z), f2t(av[2].w)); \
        *(uint4*)(Asm + asw1 + 4) = make_uint4(f2t(av[3].x), f2t(av[3].y), f2t(av[3].z), f2t(av[3].w)); \
        _Pragma("unroll") for (int j = 0; j < 4; j++) \
            *(uint4*)(Bsm + bsw[j]) = make_uint4(f2t(bv[j].x), f2t(bv[j].y), f2t(bv[j].z), f2t(bv[j].w)); \
    } while (0)

    float acc[4][4][4] = {};

    LDGA(0); STSA(0); LDGA(1);
    __syncthreads();

    for (int it = 0; it < KT; it++) {
        const int cur = it & 1;
        if (it + 1 < KT) STSA(cur ^ 1);
        if (it + 2 < KT) LDGA(it + 2);

        const uint32_t* As = sm + cur * STW;
        const uint32_t* Bs = As + AWORDS;
        #pragma unroll
        for (int ks = 0; ks < 4; ks++) {
            uint32_t af[4][4];
            #pragma unroll
            for (int mi = 0; mi < 4; mi++) {
                const int r = wm + mi * 16 + (l >> 2), c = ks * 8 + (l & 3);
                af[mi][0] = As[r * ASTR + c];
                af[mi][1] = As[(r + 8) * ASTR + c];
                af[mi][2] = As[r * ASTR + c + 4];
                af[mi][3] = As[(r + 8) * ASTR + c + 4];
            }
            uint32_t bf[4][2];
            #pragma unroll
            for (int ni = 0; ni < 4; ni++) {
                int n;
                if (G == 1) n = (ni < 2) ? (wn + ni * 8 + (l >> 2))
                                         : (64 + wn + (ni - 2) * 8 + (l >> 2));
                else        n = wn + ni * 8 + (l >> 2);
                const int k = ks * 8 + (l & 3);
                bf[ni][0] = Bs[k * BSTR + n];
                bf[ni][1] = Bs[(k + 4) * BSTR + n];
            }
            #pragma unroll
            for (int mi = 0; mi < 4; mi++)
                #pragma unroll
                for (int ni = 0; ni < 4; ni++)
                    mma8(acc[mi][ni], af[mi], bf[ni]);
        }
        __syncthreads();
    }

    // ---- epilogue ----
    #pragma unroll
    for (int mi = 0; mi < 4; mi++) {
        const int lr0 = wm + mi * 16 + (l >> 2), lr1 = lr0 + 8;
        if (G == 1) {
            #pragma unroll
            for (int ni = 0; ni < 2; ni++) {
                const int col = n0 + wn + ni * 8 + 2 * (l & 3);
                const float* g = acc[mi][ni];
                const float* u = acc[mi][ni + 2];
                if (lr0 < rows) {
                    float2 v;
                    v.x = u[0] * g[0] / (1.f + __expf(-g[0]));
                    v.y = u[1] * g[1] / (1.f + __expf(-g[1]));
                    *(float2*)&d_hbuf[(size_t)(row0 + lr0) * ITR + col] = v;
                }
                if (lr1 < rows) {
                    float2 v;
                    v.x = u[2] * g[2] / (1.f + __expf(-g[2]));
                    v.y = u[3] * g[3] / (1.f + __expf(-g[3]));
                    *(float2*)&d_hbuf[(size_t)(row0 + lr1) * ITR + col] = v;
                }
            }
        } else {
            #pragma unroll
            for (int ni = 0; ni < 4; ni++) {
                const int col = n0 + wn + ni * 8 + 2 * (l & 3);
                if (lr0 < rows)
                    *(float2*)&Out[(size_t)(row0 + lr0) * HID + col] =
                        make_float2(acc[mi][ni][0], acc[mi][ni][1]);
                if (lr1 < rows)
                    *(float2*)&Out[(size_t)(row0 + lr1) * HID + col] =
                        make_float2(acc[mi][ni][2], acc[mi][ni][3]);
            }
        }
    }
}

extern "C" void kernel_launch(void* const* d_in, const int* in_sizes, int n_in,
                              void* d_out, int out_size) {
    const float* x    = (const float*)d_in[0];
    const int*   tpe  = (const int*)d_in[1];
    const float* w1w3 = (const float*)d_in[2];
    const float* w2   = (const float*)d_in[3];
    float*       out  = (float*)d_out;

    cudaFuncSetAttribute(moe_gemm<1>, cudaFuncAttributeMaxDynamicSharedMemorySize, SMEMSZ);
    cudaFuncSetAttribute(moe_gemm<2>, cudaFuncAttributeMaxDynamicSharedMemorySize, SMEMSZ);

    setup_kernel<<<1, 32>>>(tpe);
    moe_gemm<1><<<dim3(11, 96), 256, SMEMSZ>>>(x, w1w3, nullptr);
    moe_gemm<2><<<dim3(8, 96), 256, SMEMSZ>>>(nullptr, w2, out);
}

// round 5
// speedup vs baseline: 1.4062x; 1.0495x over previous
#include <cuda_runtime.h>
#include <cstdint>

#define HID 1024
#define ITR 704
#define NEXP 32
#define TTOK 8192
#define MAXT 96
#define ASTR 36
#define BSTR 136
#define AWORDS (128*ASTR)       // 4608 words
#define BWORDS (32*BSTR)        // 4352 words
#define STW (AWORDS+BWORDS)     // 8960 words/stage
#define SMEMSZ (2*STW*4)        // 71680 bytes

__device__ int   d_te[MAXT], d_tr0[MAXT], d_trs[MAXT], d_nt;
__device__ float d_hbuf[(size_t)TTOK * ITR];

__device__ __forceinline__ uint32_t f2t(float f) {
    uint32_t r; asm("cvt.rna.tf32.f32 %0, %1;" : "=r"(r) : "f"(f)); return r;
}
__device__ __forceinline__ void mma8(float* c, const uint32_t* a, const uint32_t* b) {
    asm volatile(
        "mma.sync.aligned.m16n8k8.row.col.f32.tf32.tf32.f32 "
        "{%0,%1,%2,%3},{%4,%5,%6,%7},{%8,%9},{%0,%1,%2,%3};"
        : "+f"(c[0]), "+f"(c[1]), "+f"(c[2]), "+f"(c[3])
        : "r"(a[0]), "r"(a[1]), "r"(a[2]), "r"(a[3]), "r"(b[0]), "r"(b[1]));
}

__global__ void setup_kernel(const int* __restrict__ tpe) {
    const int e = threadIdx.x;          // 32 threads, one per expert
    const int c = tpe[e];
    const int nte = (c + 127) >> 7;
    int off = c, tb = nte;
    #pragma unroll
    for (int d = 1; d < 32; d <<= 1) {
        int o2 = __shfl_up_sync(0xffffffffu, off, d);
        int t2 = __shfl_up_sync(0xffffffffu, tb, d);
        if (e >= d) { off += o2; tb += t2; }
    }
    const int row0 = off - c, t0 = tb - nte;
    for (int i = 0; i < nte; i++) {
        d_te[t0 + i]  = e;
        d_tr0[t0 + i] = row0 + i * 128;
        d_trs[t0 + i] = min(128, c - i * 128);
    }
    if (e == 31) d_nt = tb;
}

template <int G>
__global__ __launch_bounds__(256, 2) void moe_gemm(const float* __restrict__ Ain,
                                                   const float* __restrict__ Bin,
                                                   float* __restrict__ Out) {
    extern __shared__ __align__(16) uint32_t sm[];
    const int tile = blockIdx.y;
    if (tile >= d_nt) return;
    constexpr int KT   = (G == 1) ? 32 : 22;
    constexpr int AST  = (G == 1) ? HID : ITR;
    constexpr int BROW = (G == 1) ? (2 * ITR) : HID;
    const int e = d_te[tile], row0 = d_tr0[tile], rows = d_trs[tile];
    const int n0 = blockIdx.x * ((G == 1) ? 64 : 128);

    const int tid = threadIdx.x, w = tid >> 5, l = tid & 31;
    const int wm = (w & 1) * 64;
    const int wn = (w >> 1) * ((G == 1) ? 16 : 32);

    const float* Ag = (G == 1) ? Ain : d_hbuf;
    const float* Bg = Bin + (size_t)e * ((G == 1) ? (size_t)HID * (2 * ITR)
                                                  : (size_t)ITR * HID);

    // A loads: 2 rows (ar, ar+64), 8 consecutive k each (2 float4)
    const int ar = tid >> 2, ak = (tid & 3) * 8;
    const size_t aoff0 = (size_t)min(row0 + ar, TTOK - 1) * AST + ak;
    const size_t aoff1 = (size_t)min(row0 + ar + 64, TTOK - 1) * AST + ak;
    const int asw0 = ar * ASTR + ak, asw1 = (ar + 64) * ASTR + ak;

    // B loads: row k = tid>>3, 4 cols x 4 chunks (n += 32j)
    const int bk = tid >> 3, bn = (tid & 7) * 4;
    size_t boff[4]; int bsw[4];
    #pragma unroll
    for (int j = 0; j < 4; j++) {
        int n = bn + 32 * j;
        int col = (G == 1) ? ((n < 64) ? (n0 + n) : (ITR + n0 + n - 64)) : (n0 + n);
        boff[j] = (size_t)bk * BROW + col;
        bsw[j]  = bk * BSTR + n;
    }

    float4 av[4], bv[4];
    #define LDGA(it) do { const size_t ko = (size_t)(it) * 32; \
        av[0] = *(const float4*)(Ag + aoff0 + ko); \
        av[1] = *(const float4*)(Ag + aoff0 + ko + 4); \
        av[2] = *(const float4*)(Ag + aoff1 + ko); \
        av[3] = *(const float4*)(Ag + aoff1 + ko + 4); \
        _Pragma("unroll") for (int j = 0; j < 4; j++) \
            bv[j] = *(const float4*)(Bg + boff[j] + (size_t)(it) * 32 * BROW); \
    } while (0)

    #define STSA(st) do { uint32_t* Asm = sm + (st) * STW; uint32_t* Bsm = Asm + AWORDS; \
        *(uint4*)(Asm + asw0)     = make_uint4(f2t(av[0].x), f2t(av[0].y), f2t(av[0].z), f2t(av[0].w)); \
        *(uint4*)(Asm + asw0 + 4) = make_uint4(f2t(av[1].x), f2t(av[1].y), f2t(av[1].z), f2t(av[1].w)); \
        *(uint4*)(Asm + asw1)     = make_uint4(f2t(av[2].x), f2t(av[2].y), f2t(av[2].z), f2t(av[2].w)); \
        *(uint4*)(Asm + asw1 + 4) = make_uint4(f2t(av[3].x), f2t(av[3].y), f2t(av[3].z), f2t(av[3].w)); \
        _Pragma("unroll") for (int j = 0; j < 4; j++) \
            *(uint4*)(Bsm + bsw[j]) = make_uint4(f2t(bv[j].x), f2t(bv[j].y), f2t(bv[j].z), f2t(bv[j].w)); \
    } while (0)

    float acc[4][4][4] = {};

    LDGA(0); STSA(0); LDGA(1);
    __syncthreads();

    for (int it = 0; it < KT; it++) {
        const int cur = it & 1;
        if (it + 1 < KT) STSA(cur ^ 1);
        if (it + 2 < KT) LDGA(it + 2);

        const uint32_t* As = sm + cur * STW;
        const uint32_t* Bs = As + AWORDS;
        #pragma unroll
        for (int ks = 0; ks < 4; ks++) {
            uint32_t af[4][4];
            #pragma unroll
            for (int mi = 0; mi < 4; mi++) {
                const int r = wm + mi * 16 + (l >> 2), c = ks * 8 + (l & 3);
                af[mi][0] = As[r * ASTR + c];
                af[mi][1] = As[(r + 8) * ASTR + c];
                af[mi][2] = As[r * ASTR + c + 4];
                af[mi][3] = As[(r + 8) * ASTR + c + 4];
            }
            uint32_t bf[4][2];
            #pragma unroll
            for (int ni = 0; ni < 4; ni++) {
                int n;
                if (G == 1) n = (ni < 2) ? (wn + ni * 8 + (l >> 2))
                                         : (64 + wn + (ni - 2) * 8 + (l >> 2));
                else        n = wn + ni * 8 + (l >> 2);
                const int k = ks * 8 + (l & 3);
                bf[ni][0] = Bs[k * BSTR + n];
                bf[ni][1] = Bs[(k + 4) * BSTR + n];
            }
            #pragma unroll
            for (int mi = 0; mi < 4; mi++)
                #pragma unroll
                for (int ni = 0; ni < 4; ni++)
                    mma8(acc[mi][ni], af[mi], bf[ni]);
        }
        __syncthreads();
    }

    // ---- epilogue ----
    #pragma unroll
    for (int mi = 0; mi < 4; mi++) {
        const int lr0 = wm + mi * 16 + (l >> 2), lr1 = lr0 + 8;
        if (G == 1) {
            #pragma unroll
            for (int ni = 0; ni < 2; ni++) {
                const int col = n0 + wn + ni * 8 + 2 * (l & 3);
                const float* g = acc[mi][ni];
                const float* u = acc[mi][ni + 2];
                if (lr0 < rows) {
                    float2 v;
                    v.x = u[0] * g[0] / (1.f + __expf(-g[0]));
                    v.y = u[1] * g[1] / (1.f + __expf(-g[1]));
                    *(float2*)&d_hbuf[(size_t)(row0 + lr0) * ITR + col] = v;
                }
                if (lr1 < rows) {
                    float2 v;
                    v.x = u[2] * g[2] / (1.f + __expf(-g[2]));
                    v.y = u[3] * g[3] / (1.f + __expf(-g[3]));
                    *(float2*)&d_hbuf[(size_t)(row0 + lr1) * ITR + col] = v;
                }
            }
        } else {
            #pragma unroll
            for (int ni = 0; ni < 4; ni++) {
                const int col = n0 + wn + ni * 8 + 2 * (l & 3);
                if (lr0 < rows)
                    *(float2*)&Out[(size_t)(row0 + lr0) * HID + col] =
                        make_float2(acc[mi][ni][0], acc[mi][ni][1]);
                if (lr1 < rows)
                    *(float2*)&Out[(size_t)(row0 + lr1) * HID + col] =
                        make_float2(acc[mi][ni][2], acc[mi][ni][3]);
            }
        }
    }
}

extern "C" void kernel_launch(void* const* d_in, const int* in_sizes, int n_in,
                              void* d_out, int out_size) {
    const float* x    = (const float*)d_in[0];
    const int*   tpe  = (const int*)d_in[1];
    const float* w1w3 = (const float*)d_in[2];
    const float* w2   = (const float*)d_in[3];
    float*       out  = (float*)d_out;

    cudaFuncSetAttribute(moe_gemm<1>, cudaFuncAttributeMaxDynamicSharedMemorySize, SMEMSZ);
    cudaFuncSetAttribute(moe_gemm<2>, cudaFuncAttributeMaxDynamicSharedMemorySize, SMEMSZ);

    setup_kernel<<<1, 32>>>(tpe);
    moe_gemm<1><<<dim3(11, 96), 256, SMEMSZ>>>(x, w1w3, nullptr);
    moe_gemm<2><<<dim3(8, 96), 256, SMEMSZ>>>(nullptr, w2, out);
}

// round 6
// speedup vs baseline: 1.4554x; 1.0350x over previous
#include <cuda_runtime.h>
#include <cstdint>

#define HID 1024
#define ITR 704
#define NEXP 32
#define TTOK 8192
#define MAXT 96
#define ASTR 36
#define BSTR 136
#define AWORDS (128*ASTR)       // 4608 words
#define BWORDS (32*BSTR)        // 4352 words
#define STW (AWORDS+BWORDS)     // 8960 words/stage
#define SMEMSZ (3*STW*4)        // 107520 bytes (3 stages)
#define DEBIAS 1.000705f        // 1/(1 - 2*2^-11*E[1/m]) : RZ-truncation bias fix

__device__ int   d_te[MAXT], d_tr0[MAXT], d_trs[MAXT], d_nt;
__device__ float d_hbuf[(size_t)TTOK * ITR];

__device__ __forceinline__ uint32_t smem_u32(const void* p) {
    uint32_t a;
    asm("{ .reg .u64 t; cvta.to.shared.u64 t, %1; cvt.u32.u64 %0, t; }" : "=r"(a) : "l"(p));
    return a;
}
__device__ __forceinline__ void cp16(uint32_t dst, const void* src) {
    asm volatile("cp.async.ca.shared.global [%0], [%1], 16;" :: "r"(dst), "l"(src));
}
#define CPCOMMIT() asm volatile("cp.async.commit_group;" ::: "memory")
#define CPWAIT1()  asm volatile("cp.async.wait_group 1;" ::: "memory")

__device__ __forceinline__ void mma8(float* c, const uint32_t* a, const uint32_t* b) {
    asm volatile(
        "mma.sync.aligned.m16n8k8.row.col.f32.tf32.tf32.f32 "
        "{%0,%1,%2,%3},{%4,%5,%6,%7},{%8,%9},{%0,%1,%2,%3};"
        : "+f"(c[0]), "+f"(c[1]), "+f"(c[2]), "+f"(c[3])
        : "r"(a[0]), "r"(a[1]), "r"(a[2]), "r"(a[3]), "r"(b[0]), "r"(b[1]));
}

__global__ void setup_kernel(const int* __restrict__ tpe) {
    const int e = threadIdx.x;
    const int c = tpe[e];
    const int nte = (c + 127) >> 7;
    int off = c, tb = nte;
    #pragma unroll
    for (int d = 1; d < 32; d <<= 1) {
        int o2 = __shfl_up_sync(0xffffffffu, off, d);
        int t2 = __shfl_up_sync(0xffffffffu, tb, d);
        if (e >= d) { off += o2; tb += t2; }
    }
    const int row0 = off - c, t0 = tb - nte;
    for (int i = 0; i < nte; i++) {
        d_te[t0 + i]  = e;
        d_tr0[t0 + i] = row0 + i * 128;
        d_trs[t0 + i] = min(128, c - i * 128);
    }
    if (e == 31) d_nt = tb;
}

template <int G>
__global__ __launch_bounds__(256, 2) void moe_gemm(const float* __restrict__ Ain,
                                                   const float* __restrict__ Bin,
                                                   float* __restrict__ Out) {
    extern __shared__ __align__(16) uint32_t sm[];
    const int tile = blockIdx.y;
    if (tile >= d_nt) return;
    constexpr int KT   = (G == 1) ? 32 : 22;
    constexpr int AST  = (G == 1) ? HID : ITR;
    constexpr int BROW = (G == 1) ? (2 * ITR) : HID;
    const int e = d_te[tile], row0 = d_tr0[tile], rows = d_trs[tile];
    const int n0 = blockIdx.x * ((G == 1) ? 64 : 128);

    const int tid = threadIdx.x, w = tid >> 5, l = tid & 31;
    const int wm = (w & 1) * 64;
    const int wn = (w >> 1) * ((G == 1) ? 16 : 32);
    const uint32_t smb = smem_u32(sm);

    const float* Ag = (G == 1) ? Ain : d_hbuf;
    const float* Bg = Bin + (size_t)e * ((G == 1) ? (size_t)HID * (2 * ITR)
                                                  : (size_t)ITR * HID);

    // A: 2 rows (ar, ar+64) x 8 consecutive k (2x 16B)
    const int ar = tid >> 2, ak = (tid & 3) * 8;
    const size_t aoff0 = (size_t)min(row0 + ar, TTOK - 1) * AST + ak;
    const size_t aoff1 = (size_t)min(row0 + ar + 64, TTOK - 1) * AST + ak;
    const uint32_t asw0 = (uint32_t)(ar * ASTR + ak) * 4u;
    const uint32_t asw1 = (uint32_t)((ar + 64) * ASTR + ak) * 4u;

    // B: row k = tid>>3, 4 cols x 4 chunks
    const int bk = tid >> 3, bn = (tid & 7) * 4;
    size_t boff[4]; uint32_t bsw[4];
    #pragma unroll
    for (int j = 0; j < 4; j++) {
        int n = bn + 32 * j;
        int col = (G == 1) ? ((n < 64) ? (n0 + n) : (ITR + n0 + n - 64)) : (n0 + n);
        boff[j] = (size_t)bk * BROW + col;
        bsw[j]  = (uint32_t)(AWORDS + bk * BSTR + n) * 4u;
    }

    #define CPA(it, st) do { \
        const uint32_t _b = smb + (uint32_t)(st) * (STW * 4); \
        const size_t _ko = (size_t)(it) * 32; \
        cp16(_b + asw0,      Ag + aoff0 + _ko); \
        cp16(_b + asw0 + 16, Ag + aoff0 + _ko + 4); \
        cp16(_b + asw1,      Ag + aoff1 + _ko); \
        cp16(_b + asw1 + 16, Ag + aoff1 + _ko + 4); \
        _Pragma("unroll") for (int j = 0; j < 4; j++) \
            cp16(_b + bsw[j], Bg + boff[j] + (size_t)(it) * 32 * BROW); \
    } while (0)

    float acc[4][4][4] = {};

    CPA(0, 0); CPCOMMIT();
    CPA(1, 1); CPCOMMIT();

    for (int it = 0; it < KT; it++) {
        CPWAIT1();
        __syncthreads();
        if (it + 2 < KT) CPA(it + 2, (it + 2) % 3);
        CPCOMMIT();

        const uint32_t* As = sm + (it % 3) * STW;
        const uint32_t* Bs = As + AWORDS;
        #pragma unroll
        for (int ks = 0; ks < 4; ks++) {
            uint32_t af[4][4];
            #pragma unroll
            for (int mi = 0; mi < 4; mi++) {
                const int r = wm + mi * 16 + (l >> 2), c = ks * 8 + (l & 3);
                af[mi][0] = As[r * ASTR + c];
                af[mi][1] = As[(r + 8) * ASTR + c];
                af[mi][2] = As[r * ASTR + c + 4];
                af[mi][3] = As[(r + 8) * ASTR + c + 4];
            }
            uint32_t bf[4][2];
            #pragma unroll
            for (int ni = 0; ni < 4; ni++) {
                int n;
                if (G == 1) n = (ni < 2) ? (wn + ni * 8 + (l >> 2))
                                         : (64 + wn + (ni - 2) * 8 + (l >> 2));
                else        n = wn + ni * 8 + (l >> 2);
                const int k = ks * 8 + (l & 3);
                bf[ni][0] = Bs[k * BSTR + n];
                bf[ni][1] = Bs[(k + 4) * BSTR + n];
            }
            #pragma unroll
            for (int mi = 0; mi < 4; mi++)
                #pragma unroll
                for (int ni = 0; ni < 4; ni++)
                    mma8(acc[mi][ni], af[mi], bf[ni]);
        }
        __syncthreads();
    }

    // ---- epilogue (with RZ-truncation debias) ----
    #pragma unroll
    for (int mi = 0; mi < 4; mi++) {
        const int lr0 = wm + mi * 16 + (l >> 2), lr1 = lr0 + 8;
        if (G == 1) {
            #pragma unroll
            for (int ni = 0; ni < 2; ni++) {
                const int col = n0 + wn + ni * 8 + 2 * (l & 3);
                const float* g = acc[mi][ni];
                const float* u = acc[mi][ni + 2];
                if (lr0 < rows) {
                    float g0 = g[0] * DEBIAS, g1 = g[1] * DEBIAS;
                    float2 v;
                    v.x = u[0] * DEBIAS * g0 / (1.f + __expf(-g0));
                    v.y = u[1] * DEBIAS * g1 / (1.f + __expf(-g1));
                    *(float2*)&d_hbuf[(size_t)(row0 + lr0) * ITR + col] = v;
                }
                if (lr1 < rows) {
                    float g2 = g[2] * DEBIAS, g3 = g[3] * DEBIAS;
                    float2 v;
                    v.x = u[2] * DEBIAS * g2 / (1.f + __expf(-g2));
                    v.y = u[3] * DEBIAS * g3 / (1.f + __expf(-g3));
                    *(float2*)&d_hbuf[(size_t)(row0 + lr1) * ITR + col] = v;
                }
            }
        } else {
            #pragma unroll
            for (int ni = 0; ni < 4; ni++) {
                const int col = n0 + wn + ni * 8 + 2 * (l & 3);
                if (lr0 < rows)
                    *(float2*)&Out[(size_t)(row0 + lr0) * HID + col] =
                        make_float2(acc[mi][ni][0] * DEBIAS, acc[mi][ni][1] * DEBIAS);
                if (lr1 < rows)
                    *(float2*)&Out[(size_t)(row0 + lr1) * HID + col] =
                        make_float2(acc[mi][ni][2] * DEBIAS, acc[mi][ni][3] * DEBIAS);
            }
        }
    }
}

extern "C" void kernel_launch(void* const* d_in, const int* in_sizes, int n_in,
                              void* d_out, int out_size) {
    const float* x    = (const float*)d_in[0];
    const int*   tpe  = (const int*)d_in[1];
    const float* w1w3 = (const float*)d_in[2];
    const float* w2   = (const float*)d_in[3];
    float*       out  = (float*)d_out;

    cudaFuncSetAttribute(moe_gemm<1>, cudaFuncAttributeMaxDynamicSharedMemorySize, SMEMSZ);
    cudaFuncSetAttribute(moe_gemm<2>, cudaFuncAttributeMaxDynamicSharedMemorySize, SMEMSZ);

    setup_kernel<<<1, 32>>>(tpe);
    moe_gemm<1><<<dim3(11, 96), 256, SMEMSZ>>>(x, w1w3, nullptr);
    moe_gemm<2><<<dim3(8, 96), 256, SMEMSZ>>>(nullptr, w2, out);
}

// round 7
// speedup vs baseline: 2.2407x; 1.5396x over previous
#include <cuda_runtime.h>
#include <cuda_fp16.h>
#include <cstdint>

#define HID 1024
#define ITR 704
#define NEXP 32
#define TTOK 8192
#define MAXT 96
#define ABYTES 10240            // 128 rows * 80 B
#define BBYTES 8704             // 32 rows * 272 B
#define BBASE  30720            // 3 * ABYTES
#define SMEMSZ (BBASE + 2*BBYTES)   // 48128

__device__ int d_te[MAXT], d_tr0[MAXT], d_trs[MAXT], d_nt;
__device__ unsigned short d_xh[(size_t)TTOK * HID];
__device__ unsigned short d_hbuf[(size_t)TTOK * ITR];

__device__ __forceinline__ uint32_t smem_u32(const void* p) {
    uint32_t a;
    asm("{ .reg .u64 t; cvta.to.shared.u64 t, %1; cvt.u32.u64 %0, t; }" : "=r"(a) : "l"(p));
    return a;
}
__device__ __forceinline__ void cp16(uint32_t dst, const void* src) {
    asm volatile("cp.async.ca.shared.global [%0], [%1], 16;" :: "r"(dst), "l"(src));
}
#define CPCOMMIT() asm volatile("cp.async.commit_group;" ::: "memory")
#define CPWAIT2()  asm volatile("cp.async.wait_group 2;" ::: "memory")

#define LDSM4(r, a) \
    asm volatile("ldmatrix.sync.aligned.m8n8.x4.shared.b16 {%0,%1,%2,%3}, [%4];" \
        : "=r"((r)[0]), "=r"((r)[1]), "=r"((r)[2]), "=r"((r)[3]) : "r"(a))
#define LDSM4T(r, a) \
    asm volatile("ldmatrix.sync.aligned.m8n8.x4.trans.shared.b16 {%0,%1,%2,%3}, [%4];" \
        : "=r"((r)[0]), "=r"((r)[1]), "=r"((r)[2]), "=r"((r)[3]) : "r"(a))

__device__ __forceinline__ void mma16(float* c, const uint32_t* a, const uint32_t* b) {
    asm volatile(
        "mma.sync.aligned.m16n8k16.row.col.f32.f16.f16.f32 "
        "{%0,%1,%2,%3},{%4,%5,%6,%7},{%8,%9},{%0,%1,%2,%3};"
        : "+f"(c[0]), "+f"(c[1]), "+f"(c[2]), "+f"(c[3])
        : "r"(a[0]), "r"(a[1]), "r"(a[2]), "r"(a[3]), "r"(b[0]), "r"(b[1]));
}
__device__ __forceinline__ uint32_t h2u(__half2 h) { return *(uint32_t*)&h; }

__global__ void setup_kernel(const int* __restrict__ tpe) {
    const int e = threadIdx.x;
    const int c = tpe[e];
    const int nte = (c + 127) >> 7;
    int off = c, tb = nte;
    #pragma unroll
    for (int d = 1; d < 32; d <<= 1) {
        int o2 = __shfl_up_sync(0xffffffffu, off, d);
        int t2 = __shfl_up_sync(0xffffffffu, tb, d);
        if (e >= d) { off += o2; tb += t2; }
    }
    const int row0 = off - c, t0 = tb - nte;
    for (int i = 0; i < nte; i++) {
        d_te[t0 + i]  = e;
        d_tr0[t0 + i] = row0 + i * 128;
        d_trs[t0 + i] = min(128, c - i * 128);
    }
    if (e == 31) d_nt = tb;
}

__global__ void prep_kernel(const float* __restrict__ x) {
    const size_t i = ((size_t)blockIdx.x * 256 + threadIdx.x) * 8;
    float4 v0 = *(const float4*)(x + i);
    float4 v1 = *(const float4*)(x + i + 4);
    uint4 q;
    q.x = h2u(__floats2half2_rn(v0.x, v0.y));
    q.y = h2u(__floats2half2_rn(v0.z, v0.w));
    q.z = h2u(__floats2half2_rn(v1.x, v1.y));
    q.w = h2u(__floats2half2_rn(v1.z, v1.w));
    *(uint4*)(d_xh + i) = q;
}

template <int G>
__global__ __launch_bounds__(256, 2) void moe_gemm(const float* __restrict__ Bin,
                                                   float* __restrict__ Out) {
    extern __shared__ __align__(16) char sm[];
    const int tile = blockIdx.y;
    if (tile >= d_nt) return;
    constexpr int KT   = (G == 1) ? 32 : 22;
    constexpr int AST  = (G == 1) ? HID : ITR;          // A row stride (halves)
    constexpr int BROW = (G == 1) ? (2 * ITR) : HID;    // B row stride (floats)
    const int e = d_te[tile], row0 = d_tr0[tile], rows = d_trs[tile];
    const int n0 = blockIdx.x * ((G == 1) ? 64 : 128);

    const int tid = threadIdx.x, w = tid >> 5, l = tid & 31;
    const int wm = (w & 1) * 64;
    const int wn = (w >> 1) * ((G == 1) ? 16 : 32);
    const uint32_t smb = smem_u32(sm);

    const unsigned short* Ah = (G == 1) ? d_xh : d_hbuf;
    const float* Bg = Bin + (size_t)e * ((G == 1) ? (size_t)HID * (2 * ITR)
                                                  : (size_t)ITR * HID);

    // A staging: 2 rows x 8 halves via cp.async
    const int ar0 = tid >> 2, ar1 = ar0 + 64, ka = (tid & 3) * 8;
    const size_t ga0 = (size_t)min(row0 + ar0, TTOK - 1) * AST + ka;
    const size_t ga1 = (size_t)min(row0 + ar1, TTOK - 1) * AST + ka;
    const uint32_t ad0 = (uint32_t)(ar0 * 80 + ka * 2);
    const uint32_t ad1 = (uint32_t)(ar1 * 80 + ka * 2);

    // B staging: row k = tid>>3, 16 n starting at (tid&7)*16
    const int kb = tid >> 3, nb = (tid & 7) * 16;
    size_t boff[4];
    #pragma unroll
    for (int j = 0; j < 4; j++) {
        int nloc = nb + 4 * j;
        int col = (G == 1) ? ((nloc < 64) ? (n0 + nloc) : (ITR + n0 + nloc - 64))
                           : (n0 + nloc);
        boff[j] = (size_t)kb * BROW + col;
    }
    const int bofs = kb * 272 + nb * 2;

    #define CPA(it) do { if ((it) < KT) { \
        const uint32_t _d = smb + (uint32_t)(((it) % 3) * ABYTES); \
        const size_t _ko = (size_t)(it) * 32; \
        cp16(_d + ad0, Ah + ga0 + _ko); \
        cp16(_d + ad1, Ah + ga1 + _ko); } } while (0)

    float4 bv[4];
    #define LDGB(it) do { if ((it) < KT) { \
        _Pragma("unroll") for (int j = 0; j < 4; j++) \
            bv[j] = *(const float4*)(Bg + boff[j] + (size_t)(it) * 32 * BROW); } } while (0)

    #define STSB(st) do { \
        char* _p = sm + BBASE + (st) * BBYTES + bofs; \
        uint4 q0, q1; \
        q0.x = h2u(__floats2half2_rn(bv[0].x, bv[0].y)); \
        q0.y = h2u(__floats2half2_rn(bv[0].z, bv[0].w)); \
        q0.z = h2u(__floats2half2_rn(bv[1].x, bv[1].y)); \
        q0.w = h2u(__floats2half2_rn(bv[1].z, bv[1].w)); \
        q1.x = h2u(__floats2half2_rn(bv[2].x, bv[2].y)); \
        q1.y = h2u(__floats2half2_rn(bv[2].z, bv[2].w)); \
        q1.z = h2u(__floats2half2_rn(bv[3].x, bv[3].y)); \
        q1.w = h2u(__floats2half2_rn(bv[3].z, bv[3].w)); \
        *(uint4*)_p = q0; \
        *(uint4*)(_p + 16) = q1; \
    } while (0)

    float acc[4][4][4] = {};

    CPA(0); CPCOMMIT();
    CPA(1); CPCOMMIT();
    LDGB(0); STSB(0); LDGB(1);

    for (int it = 0; it < KT; it++) {
        const int cur = it & 1;
        CPA(it + 2); CPCOMMIT();
        if (it + 1 < KT) STSB(cur ^ 1);
        LDGB(it + 2);
        CPWAIT2();
        __syncthreads();

        const uint32_t Asb = smb + (uint32_t)((it % 3) * ABYTES);
        const uint32_t Bsb = smb + BBASE + cur * BBYTES;
        const int lr = (l & 7) + ((l >> 3) & 1) * 8;
        const int lc = (l >> 4) * 8;

        #pragma unroll
        for (int ks = 0; ks < 2; ks++) {
            uint32_t a[4][4];
            #pragma unroll
            for (int mi = 0; mi < 4; mi++) {
                uint32_t ad = Asb + (uint32_t)((wm + mi * 16 + lr) * 80 + (ks * 16 + lc) * 2);
                LDSM4(a[mi], ad);
            }
            const int nA = wn;
            const int nB = (G == 1) ? (64 + wn) : (wn + 16);
            uint32_t bA[4], bB[4];
            uint32_t bd = Bsb + (uint32_t)((ks * 16 + lr) * 272);
            LDSM4T(bA, bd + (nA + lc) * 2);
            LDSM4T(bB, bd + (nB + lc) * 2);
            #pragma unroll
            for (int mi = 0; mi < 4; mi++) {
                mma16(acc[mi][0], a[mi], bA + 0);
                mma16(acc[mi][1], a[mi], bA + 2);
                mma16(acc[mi][2], a[mi], bB + 0);
                mma16(acc[mi][3], a[mi], bB + 2);
            }
        }
        __syncthreads();
    }

    // ---- epilogue ----
    #pragma unroll
    for (int mi = 0; mi < 4; mi++) {
        const int lr0 = wm + mi * 16 + (l >> 2), lr1 = lr0 + 8;
        if (G == 1) {
            #pragma unroll
            for (int ni = 0; ni < 2; ni++) {
                const int col = n0 + wn + ni * 8 + 2 * (l & 3);
                const float* g = acc[mi][ni];
                const float* u = acc[mi][ni + 2];
                if (lr0 < rows) {
                    float s0 = g[0] / (1.f + __expf(-g[0]));
                    float s1 = g[1] / (1.f + __expf(-g[1]));
                    __half2 h = __floats2half2_rn(u[0] * s0, u[1] * s1);
                    *(uint32_t*)(d_hbuf + (size_t)(row0 + lr0) * ITR + col) = h2u(h);
                }
                if (lr1 < rows) {
                    float s2 = g[2] / (1.f + __expf(-g[2]));
                    float s3 = g[3] / (1.f + __expf(-g[3]));
                    __half2 h = __floats2half2_rn(u[2] * s2, u[3] * s3);
                    *(uint32_t*)(d_hbuf + (size_t)(row0 + lr1) * ITR + col) = h2u(h);
                }
            }
        } else {
            #pragma unroll
            for (int ni = 0; ni < 4; ni++) {
                const int col = n0 + wn + ni * 8 + 2 * (l & 3);
                if (lr0 < rows)
                    *(float2*)&Out[(size_t)(row0 + lr0) * HID + col] =
                        make_float2(acc[mi][ni][0], acc[mi][ni][1]);
                if (lr1 < rows)
                    *(float2*)&Out[(size_t)(row0 + lr1) * HID + col] =
                        make_float2(acc[mi][ni][2], acc[mi][ni][3]);
            }
        }
    }
}

extern "C" void kernel_launch(void* const* d_in, const int* in_sizes, int n_in,
                              void* d_out, int out_size) {
    const float* x    = (const float*)d_in[0];
    const int*   tpe  = (const int*)d_in[1];
    const float* w1w3 = (const float*)d_in[2];
    const float* w2   = (const float*)d_in[3];
    float*       out  = (float*)d_out;

    cudaFuncSetAttribute(moe_gemm<1>, cudaFuncAttributeMaxDynamicSharedMemorySize, SMEMSZ);
    cudaFuncSetAttribute(moe_gemm<2>, cudaFuncAttributeMaxDynamicSharedMemorySize, SMEMSZ);

    setup_kernel<<<1, 32>>>(tpe);
    prep_kernel<<<TTOK * HID / 2048, 256>>>(x);
    moe_gemm<1><<<dim3(11, 96), 256, SMEMSZ>>>(w1w3, nullptr);
    moe_gemm<2><<<dim3(8, 96), 256, SMEMSZ>>>(w2, out);
}

// round 8
// speedup vs baseline: 2.3263x; 1.0382x over previous
#include <cuda_runtime.h>
#include <cuda_fp16.h>
#include <cstdint>

#define HID 1024
#define ITR 704
#define NEXP 32
#define TTOK 8192
#define MAXT 96
#define ABYTES 10240            // 128 rows * 80 B
#define BBYTES 8704             // 32 rows * 272 B
#define BBASE  30720            // 3 * ABYTES
#define SMEMSZ (BBASE + 2*BBYTES)   // 48128

__device__ int d_te[MAXT], d_tr0[MAXT], d_trs[MAXT], d_nt;
__device__ unsigned short d_xh[(size_t)TTOK * HID];
__device__ unsigned short d_hbuf[(size_t)TTOK * ITR];

__device__ __forceinline__ uint32_t smem_u32(const void* p) {
    uint32_t a;
    asm("{ .reg .u64 t; cvta.to.shared.u64 t, %1; cvt.u32.u64 %0, t; }" : "=r"(a) : "l"(p));
    return a;
}
__device__ __forceinline__ void cp16(uint32_t dst, const void* src) {
    asm volatile("cp.async.ca.shared.global [%0], [%1], 16;" :: "r"(dst), "l"(src));
}
#define CPCOMMIT() asm volatile("cp.async.commit_group;" ::: "memory")
#define CPWAIT2()  asm volatile("cp.async.wait_group 2;" ::: "memory")

#define LDSM4(r, a) \
    asm volatile("ldmatrix.sync.aligned.m8n8.x4.shared.b16 {%0,%1,%2,%3}, [%4];" \
        : "=r"((r)[0]), "=r"((r)[1]), "=r"((r)[2]), "=r"((r)[3]) : "r"(a))
#define LDSM4T(r, a) \
    asm volatile("ldmatrix.sync.aligned.m8n8.x4.trans.shared.b16 {%0,%1,%2,%3}, [%4];" \
        : "=r"((r)[0]), "=r"((r)[1]), "=r"((r)[2]), "=r"((r)[3]) : "r"(a))

__device__ __forceinline__ void mma16(float* c, const uint32_t* a, const uint32_t* b) {
    asm volatile(
        "mma.sync.aligned.m16n8k16.row.col.f32.f16.f16.f32 "
        "{%0,%1,%2,%3},{%4,%5,%6,%7},{%8,%9},{%0,%1,%2,%3};"
        : "+f"(c[0]), "+f"(c[1]), "+f"(c[2]), "+f"(c[3])
        : "r"(a[0]), "r"(a[1]), "r"(a[2]), "r"(a[3]), "r"(b[0]), "r"(b[1]));
}
__device__ __forceinline__ uint32_t h2u(__half2 h) { return *(uint32_t*)&h; }

// prep: convert x -> fp16; block 0 / warp 0 additionally builds the tile list
__global__ void prep_kernel(const float* __restrict__ x, const int* __restrict__ tpe) {
    if (blockIdx.x == 0 && threadIdx.x < 32) {
        const int e = threadIdx.x;
        const int c = tpe[e];
        const int nte = (c + 127) >> 7;
        int off = c, tb = nte;
        #pragma unroll
        for (int d = 1; d < 32; d <<= 1) {
            int o2 = __shfl_up_sync(0xffffffffu, off, d);
            int t2 = __shfl_up_sync(0xffffffffu, tb, d);
            if (e >= d) { off += o2; tb += t2; }
        }
        const int row0 = off - c, t0 = tb - nte;
        for (int i = 0; i < nte; i++) {
            d_te[t0 + i]  = e;
            d_tr0[t0 + i] = row0 + i * 128;
            d_trs[t0 + i] = min(128, c - i * 128);
        }
        if (e == 31) d_nt = tb;
    }
    const size_t i = ((size_t)blockIdx.x * 256 + threadIdx.x) * 8;
    float4 v0 = *(const float4*)(x + i);
    float4 v1 = *(const float4*)(x + i + 4);
    uint4 q;
    q.x = h2u(__floats2half2_rn(v0.x, v0.y));
    q.y = h2u(__floats2half2_rn(v0.z, v0.w));
    q.z = h2u(__floats2half2_rn(v1.x, v1.y));
    q.w = h2u(__floats2half2_rn(v1.z, v1.w));
    *(uint4*)(d_xh + i) = q;
}

template <int G>
__global__ __launch_bounds__(256, 2) void moe_gemm(const float* __restrict__ Bin,
                                                   float* __restrict__ Out) {
    extern __shared__ __align__(16) char sm[];
    const int tile = blockIdx.y;
    if (tile >= d_nt) return;
    constexpr int KT   = (G == 1) ? 32 : 22;
    constexpr int AST  = (G == 1) ? HID : ITR;          // A row stride (halves)
    constexpr int BROW = (G == 1) ? (2 * ITR) : HID;    // B row stride (floats)
    const int e = d_te[tile], row0 = d_tr0[tile], rows = d_trs[tile];
    const int n0 = blockIdx.x * ((G == 1) ? 64 : 128);

    const int tid = threadIdx.x, w = tid >> 5, l = tid & 31;
    const int wm = (w & 1) * 64;
    const int wn = (w >> 1) * ((G == 1) ? 16 : 32);
    const uint32_t smb = smem_u32(sm);

    // how many 16-row M sub-tiles of this warp hold real rows
    const int mi_max = min(4, max(0, (rows - wm + 15) >> 4));

    const unsigned short* Ah = (G == 1) ? d_xh : d_hbuf;
    const float* Bg = Bin + (size_t)e * ((G == 1) ? (size_t)HID * (2 * ITR)
                                                  : (size_t)ITR * HID);

    // A staging: 2 rows x 8 halves via cp.async
    const int ar0 = tid >> 2, ar1 = ar0 + 64, ka = (tid & 3) * 8;
    const size_t ga0 = (size_t)min(row0 + ar0, TTOK - 1) * AST + ka;
    const size_t ga1 = (size_t)min(row0 + ar1, TTOK - 1) * AST + ka;
    const uint32_t ad0 = (uint32_t)(ar0 * 80 + ka * 2);
    const uint32_t ad1 = (uint32_t)(ar1 * 80 + ka * 2);

    // B staging: row k = tid>>3, 16 n starting at (tid&7)*16
    const int kb = tid >> 3, nb = (tid & 7) * 16;
    size_t boff[4];
    #pragma unroll
    for (int j = 0; j < 4; j++) {
        int nloc = nb + 4 * j;
        int col = (G == 1) ? ((nloc < 64) ? (n0 + nloc) : (ITR + n0 + nloc - 64))
                           : (n0 + nloc);
        boff[j] = (size_t)kb * BROW + col;
    }
    const int bofs = kb * 272 + nb * 2;

    #define CPA(it) do { if ((it) < KT) { \
        const uint32_t _d = smb + (uint32_t)(((it) % 3) * ABYTES); \
        const size_t _ko = (size_t)(it) * 32; \
        cp16(_d + ad0, Ah + ga0 + _ko); \
        cp16(_d + ad1, Ah + ga1 + _ko); } } while (0)

    float4 bv[4];
    #define LDGB(it) do { if ((it) < KT) { \
        _Pragma("unroll") for (int j = 0; j < 4; j++) \
            bv[j] = *(const float4*)(Bg + boff[j] + (size_t)(it) * 32 * BROW); } } while (0)

    #define STSB(st) do { \
        char* _p = sm + BBASE + (st) * BBYTES + bofs; \
        uint4 q0, q1; \
        q0.x = h2u(__floats2half2_rn(bv[0].x, bv[0].y)); \
        q0.y = h2u(__floats2half2_rn(bv[0].z, bv[0].w)); \
        q0.z = h2u(__floats2half2_rn(bv[1].x, bv[1].y)); \
        q0.w = h2u(__floats2half2_rn(bv[1].z, bv[1].w)); \
        q1.x = h2u(__floats2half2_rn(bv[2].x, bv[2].y)); \
        q1.y = h2u(__floats2half2_rn(bv[2].z, bv[2].w)); \
        q1.z = h2u(__floats2half2_rn(bv[3].x, bv[3].y)); \
        q1.w = h2u(__floats2half2_rn(bv[3].z, bv[3].w)); \
        *(uint4*)_p = q0; \
        *(uint4*)(_p + 16) = q1; \
    } while (0)

    float acc[4][4][4] = {};

    CPA(0); CPCOMMIT();
    CPA(1); CPCOMMIT();
    LDGB(0); STSB(0); LDGB(1);

    for (int it = 0; it < KT; it++) {
        const int cur = it & 1;
        CPA(it + 2); CPCOMMIT();
        if (it + 1 < KT) STSB(cur ^ 1);
        LDGB(it + 2);
        CPWAIT2();
        __syncthreads();

        if (mi_max > 0) {
            const uint32_t Asb = smb + (uint32_t)((it % 3) * ABYTES);
            const uint32_t Bsb = smb + BBASE + cur * BBYTES;
            const int lr = (l & 7) + ((l >> 3) & 1) * 8;
            const int lc = (l >> 4) * 8;

            #pragma unroll
            for (int ks = 0; ks < 2; ks++) {
                uint32_t a[4][4];
                #pragma unroll
                for (int mi = 0; mi < 4; mi++) {
                    if (mi < mi_max) {
                        uint32_t ad = Asb + (uint32_t)((wm + mi * 16 + lr) * 80 + (ks * 16 + lc) * 2);
                        LDSM4(a[mi], ad);
                    }
                }
                const int nA = wn;
                const int nB = (G == 1) ? (64 + wn) : (wn + 16);
                uint32_t bA[4], bB[4];
                uint32_t bd = Bsb + (uint32_t)((ks * 16 + lr) * 272);
                LDSM4T(bA, bd + (nA + lc) * 2);
                LDSM4T(bB, bd + (nB + lc) * 2);
                #pragma unroll
                for (int mi = 0; mi < 4; mi++) {
                    if (mi < mi_max) {
                        mma16(acc[mi][0], a[mi], bA + 0);
                        mma16(acc[mi][1], a[mi], bA + 2);
                        mma16(acc[mi][2], a[mi], bB + 0);
                        mma16(acc[mi][3], a[mi], bB + 2);
                    }
                }
            }
        }
        __syncthreads();
    }

    // ---- epilogue ----
    #pragma unroll
    for (int mi = 0; mi < 4; mi++) {
        const int lr0 = wm + mi * 16 + (l >> 2), lr1 = lr0 + 8;
        if (G == 1) {
            #pragma unroll
            for (int ni = 0; ni < 2; ni++) {
                const int col = n0 + wn + ni * 8 + 2 * (l & 3);
                const float* g = acc[mi][ni];
                const float* u = acc[mi][ni + 2];
                if (lr0 < rows) {
                    float s0 = g[0] / (1.f + __expf(-g[0]));
                    float s1 = g[1] / (1.f + __expf(-g[1]));
                    __half2 h = __floats2half2_rn(u[0] * s0, u[1] * s1);
                    *(uint32_t*)(d_hbuf + (size_t)(row0 + lr0) * ITR + col) = h2u(h);
                }
                if (lr1 < rows) {
                    float s2 = g[2] / (1.f + __expf(-g[2]));
                    float s3 = g[3] / (1.f + __expf(-g[3]));
                    __half2 h = __floats2half2_rn(u[2] * s2, u[3] * s3);
                    *(uint32_t*)(d_hbuf + (size_t)(row0 + lr1) * ITR + col) = h2u(h);
                }
            }
        } else {
            #pragma unroll
            for (int ni = 0; ni < 4; ni++) {
                const int col = n0 + wn + ni * 8 + 2 * (l & 3);
                if (lr0 < rows)
                    *(float2*)&Out[(size_t)(row0 + lr0) * HID + col] =
                        make_float2(acc[mi][ni][0], acc[mi][ni][1]);
                if (lr1 < rows)
                    *(float2*)&Out[(size_t)(row0 + lr1) * HID + col] =
                        make_float2(acc[mi][ni][2], acc[mi][ni][3]);
            }
        }
    }
}

extern "C" void kernel_launch(void* const* d_in, const int* in_sizes, int n_in,
                              void* d_out, int out_size) {
    const float* x    = (const float*)d_in[0];
    const int*   tpe  = (const int*)d_in[1];
    const float* w1w3 = (const float*)d_in[2];
    const float* w2   = (const float*)d_in[3];
    float*       out  = (float*)d_out;

    cudaFuncSetAttribute(moe_gemm<1>, cudaFuncAttributeMaxDynamicSharedMemorySize, SMEMSZ);
    cudaFuncSetAttribute(moe_gemm<2>, cudaFuncAttributeMaxDynamicSharedMemorySize, SMEMSZ);

    prep_kernel<<<TTOK * HID / 2048, 256>>>(x, tpe);
    moe_gemm<1><<<dim3(11, 96), 256, SMEMSZ>>>(w1w3, nullptr);
    moe_gemm<2><<<dim3(8, 96), 256, SMEMSZ>>>(w2, out);
}

// round 9
// speedup vs baseline: 2.4063x; 1.0344x over previous
#include <cuda_runtime.h>
#include <cuda_fp16.h>
#include <cstdint>

#define HID 1024
#define ITR 704
#define NEXP 32
#define TTOK 8192
#define MAXT 64
#define BM 256
#define ABYTES (256*80)             // 20480
#define BBASE  (3*ABYTES)           // 61440
#define BBYTES (32*144)             // 4608
#define SMEMSZ (BBASE + 2*BBYTES)   // 70656

__device__ int d_te[MAXT], d_tr0[MAXT], d_trs[MAXT], d_nt;
__device__ unsigned short d_xh[(size_t)TTOK * HID];
__device__ unsigned short d_hbuf[(size_t)TTOK * ITR];

__device__ __forceinline__ uint32_t smem_u32(const void* p) {
    uint32_t a;
    asm("{ .reg .u64 t; cvta.to.shared.u64 t, %1; cvt.u32.u64 %0, t; }" : "=r"(a) : "l"(p));
    return a;
}
__device__ __forceinline__ void cp16(uint32_t dst, const void* src) {
    asm volatile("cp.async.ca.shared.global [%0], [%1], 16;" :: "r"(dst), "l"(src));
}
#define CPCOMMIT() asm volatile("cp.async.commit_group;" ::: "memory")
#define CPWAIT2()  asm volatile("cp.async.wait_group 2;" ::: "memory")

#define LDSM4(r, a) \
    asm volatile("ldmatrix.sync.aligned.m8n8.x4.shared.b16 {%0,%1,%2,%3}, [%4];" \
        : "=r"((r)[0]), "=r"((r)[1]), "=r"((r)[2]), "=r"((r)[3]) : "r"(a))
#define LDSM4T(r, a) \
    asm volatile("ldmatrix.sync.aligned.m8n8.x4.trans.shared.b16 {%0,%1,%2,%3}, [%4];" \
        : "=r"((r)[0]), "=r"((r)[1]), "=r"((r)[2]), "=r"((r)[3]) : "r"(a))

__device__ __forceinline__ void mma16(float* c, const uint32_t* a, const uint32_t* b) {
    asm volatile(
        "mma.sync.aligned.m16n8k16.row.col.f32.f16.f16.f32 "
        "{%0,%1,%2,%3},{%4,%5,%6,%7},{%8,%9},{%0,%1,%2,%3};"
        : "+f"(c[0]), "+f"(c[1]), "+f"(c[2]), "+f"(c[3])
        : "r"(a[0]), "r"(a[1]), "r"(a[2]), "r"(a[3]), "r"(b[0]), "r"(b[1]));
}
__device__ __forceinline__ uint32_t h2u(__half2 h) { return *(uint32_t*)&h; }

__global__ void prep_kernel(const float* __restrict__ x, const int* __restrict__ tpe) {
    if (blockIdx.x == 0 && threadIdx.x < 32) {
        const int e = threadIdx.x;
        const int c = tpe[e];
        const int nte = (c + BM - 1) / BM;
        int off = c, tb = nte;
        #pragma unroll
        for (int d = 1; d < 32; d <<= 1) {
            int o2 = __shfl_up_sync(0xffffffffu, off, d);
            int t2 = __shfl_up_sync(0xffffffffu, tb, d);
            if (e >= d) { off += o2; tb += t2; }
        }
        const int row0 = off - c, t0 = tb - nte;
        for (int i = 0; i < nte; i++) {
            d_te[t0 + i]  = e;
            d_tr0[t0 + i] = row0 + i * BM;
            d_trs[t0 + i] = min(BM, c - i * BM);
        }
        if (e == 31) d_nt = tb;
    }
    const size_t i = ((size_t)blockIdx.x * 256 + threadIdx.x) * 8;
    float4 v0 = *(const float4*)(x + i);
    float4 v1 = *(const float4*)(x + i + 4);
    uint4 q;
    q.x = h2u(__floats2half2_rn(v0.x, v0.y));
    q.y = h2u(__floats2half2_rn(v0.z, v0.w));
    q.z = h2u(__floats2half2_rn(v1.x, v1.y));
    q.w = h2u(__floats2half2_rn(v1.z, v1.w));
    *(uint4*)(d_xh + i) = q;
}

template <int G>
__global__ __launch_bounds__(256, 2) void moe_gemm(const float* __restrict__ Bin,
                                                   float* __restrict__ Out) {
    extern __shared__ __align__(16) char sm[];
    const int tile = blockIdx.y;
    if (tile >= d_nt) return;
    constexpr int KT   = (G == 1) ? 32 : 22;
    constexpr int AST  = (G == 1) ? HID : ITR;          // A row stride (halves)
    constexpr int BROW = (G == 1) ? (2 * ITR) : HID;    // B row stride (floats)
    const int e = d_te[tile], row0 = d_tr0[tile], rows = d_trs[tile];
    const int n0 = blockIdx.x * ((G == 1) ? 32 : 64);

    const int tid = threadIdx.x, w = tid >> 5, l = tid & 31;
    const int wm = (w >> 1) * 64;        // 4 M bands of 64
    const int wn = (w & 1) * 16;         // 2 N bands of 16
    const uint32_t smb = smem_u32(sm);

    const int mi_max = min(4, max(0, (rows - wm + 15) >> 4));

    const unsigned short* Ah = (G == 1) ? d_xh : d_hbuf;
    const float* Bg = Bin + (size_t)e * ((G == 1) ? (size_t)HID * (2 * ITR)
                                                  : (size_t)ITR * HID);

    // A staging: 4 rows (ar+64i) x 8 halves via cp.async
    const int ar = tid >> 2, ka = (tid & 3) * 8;
    size_t ga[4]; uint32_t ad[4];
    #pragma unroll
    for (int i = 0; i < 4; i++) {
        ga[i] = (size_t)min(row0 + ar + 64 * i, TTOK - 1) * AST + ka;
        ad[i] = (uint32_t)((ar + 64 * i) * 80 + ka * 2);
    }

    // B staging: row kb = tid>>3, 8 cols at nb (2 float4)
    const int kb = tid >> 3, nb = (tid & 7) * 8;
    size_t boff[2];
    #pragma unroll
    for (int j = 0; j < 2; j++) {
        int nloc = nb + 4 * j;
        int col = (G == 1) ? ((nloc < 32) ? (n0 + nloc) : (ITR + n0 + nloc - 32))
                           : (n0 + nloc);
        boff[j] = (size_t)kb * BROW + col;
    }
    const int bofs = kb * 144 + nb * 2;

    #define CPA(it) do { if ((it) < KT) { \
        const uint32_t _d = smb + (uint32_t)(((it) % 3) * ABYTES); \
        const size_t _ko = (size_t)(it) * 32; \
        cp16(_d + ad[0], Ah + ga[0] + _ko); \
        cp16(_d + ad[1], Ah + ga[1] + _ko); \
        cp16(_d + ad[2], Ah + ga[2] + _ko); \
        cp16(_d + ad[3], Ah + ga[3] + _ko); } } while (0)

    float4 bv[2];
    #define LDGB(it) do { if ((it) < KT) { \
        bv[0] = *(const float4*)(Bg + boff[0] + (size_t)(it) * 32 * BROW); \
        bv[1] = *(const float4*)(Bg + boff[1] + (size_t)(it) * 32 * BROW); } } while (0)

    #define STSB(st) do { \
        char* _p = sm + BBASE + (st) * BBYTES + bofs; \
        uint4 q; \
        q.x = h2u(__floats2half2_rn(bv[0].x, bv[0].y)); \
        q.y = h2u(__floats2half2_rn(bv[0].z, bv[0].w)); \
        q.z = h2u(__floats2half2_rn(bv[1].x, bv[1].y)); \
        q.w = h2u(__floats2half2_rn(bv[1].z, bv[1].w)); \
        *(uint4*)_p = q; \
    } while (0)

    float acc[4][4][4] = {};

    CPA(0); CPCOMMIT();
    CPA(1); CPCOMMIT();
    LDGB(0); STSB(0); LDGB(1);

    for (int it = 0; it < KT; it++) {
        const int cur = it & 1;
        CPA(it + 2); CPCOMMIT();
        if (it + 1 < KT) STSB(cur ^ 1);
        LDGB(it + 2);
        CPWAIT2();
        __syncthreads();

        if (mi_max > 0) {
            const uint32_t Asb = smb + (uint32_t)((it % 3) * ABYTES);
            const uint32_t Bsb = smb + BBASE + cur * BBYTES;
            const int lr = (l & 7) + ((l >> 3) & 1) * 8;
            const int lc = (l >> 4) * 8;

            #pragma unroll
            for (int ks = 0; ks < 2; ks++) {
                uint32_t a[4][4];
                #pragma unroll
                for (int mi = 0; mi < 4; mi++) {
                    if (mi < mi_max) {
                        uint32_t aadr = Asb + (uint32_t)((wm + mi * 16 + lr) * 80 + (ks * 16 + lc) * 2);
                        LDSM4(a[mi], aadr);
                    }
                }
                // G1: nA = gate cols (wn), nB = up cols (32+wn)
                // G2: nA = wn, nB = wn+32  (warp covers 32 of 64 cols? no: wn in {0,16}; cols wn and wn+32)
                const int nA = wn;
                const int nB = 32 + wn;
                uint32_t bA[4], bB[4];
                uint32_t bd = Bsb + (uint32_t)((ks * 16 + lr) * 144);
                LDSM4T(bA, bd + (nA + lc) * 2);
                LDSM4T(bB, bd + (nB + lc) * 2);
                #pragma unroll
                for (int mi = 0; mi < 4; mi++) {
                    if (mi < mi_max) {
                        mma16(acc[mi][0], a[mi], bA + 0);
                        mma16(acc[mi][1], a[mi], bA + 2);
                        mma16(acc[mi][2], a[mi], bB + 0);
                        mma16(acc[mi][3], a[mi], bB + 2);
                    }
                }
            }
        }
        __syncthreads();
    }

    // ---- epilogue ----
    #pragma unroll
    for (int mi = 0; mi < 4; mi++) {
        const int lr0 = wm + mi * 16 + (l >> 2), lr1 = lr0 + 8;
        if (G == 1) {
            // ni 0,1 = gate cols (n0+wn..), ni 2,3 = up (same h col)
            #pragma unroll
            for (int ni = 0; ni < 2; ni++) {
                const int col = n0 + wn + ni * 8 + 2 * (l & 3);
                const float* g = acc[mi][ni];
                const float* u = acc[mi][ni + 2];
                if (lr0 < rows) {
                    float s0 = g[0] / (1.f + __expf(-g[0]));
                    float s1 = g[1] / (1.f + __expf(-g[1]));
                    __half2 h = __floats2half2_rn(u[0] * s0, u[1] * s1);
                    *(uint32_t*)(d_hbuf + (size_t)(row0 + lr0) * ITR + col) = h2u(h);
                }
                if (lr1 < rows) {
                    float s2 = g[2] / (1.f + __expf(-g[2]));
                    float s3 = g[3] / (1.f + __expf(-g[3]));
                    __half2 h = __floats2half2_rn(u[2] * s2, u[3] * s3);
                    *(uint32_t*)(d_hbuf + (size_t)(row0 + lr1) * ITR + col) = h2u(h);
                }
            }
        } else {
            // ni 0,1 -> cols wn..; ni 2,3 -> cols 32+wn..
            #pragma unroll
            for (int ni = 0; ni < 4; ni++) {
                const int col = n0 + ((ni < 2) ? (wn + ni * 8) : (32 + wn + (ni - 2) * 8))
                                + 2 * (l & 3);
                if (lr0 < rows)
                    *(float2*)&Out[(size_t)(row0 + lr0) * HID + col] =
                        make_float2(acc[mi][ni][0], acc[mi][ni][1]);
                if (lr1 < rows)
                    *(float2*)&Out[(size_t)(row0 + lr1) * HID + col] =
                        make_float2(acc[mi][ni][2], acc[mi][ni][3]);
            }
        }
    }
}

extern "C" void kernel_launch(void* const* d_in, const int* in_sizes, int n_in,
                              void* d_out, int out_size) {
    const float* x    = (const float*)d_in[0];
    const int*   tpe  = (const int*)d_in[1];
    const float* w1w3 = (const float*)d_in[2];
    const float* w2   = (const float*)d_in[3];
    float*       out  = (float*)d_out;

    cudaFuncSetAttribute(moe_gemm<1>, cudaFuncAttributeMaxDynamicSharedMemorySize, SMEMSZ);
    cudaFuncSetAttribute(moe_gemm<2>, cudaFuncAttributeMaxDynamicSharedMemorySize, SMEMSZ);

    prep_kernel<<<TTOK * HID / 2048, 256>>>(x, tpe);
    moe_gemm<1><<<dim3(22, 64), 256, SMEMSZ>>>(w1w3, nullptr);
    moe_gemm<2><<<dim3(16, 64), 256, SMEMSZ>>>(w2, out);
}